// round 1
// baseline (speedup 1.0000x reference)
#include <cuda_runtime.h>
#include <math.h>

#define MTOT 16384
#define CDIM 512

// Scratch (no allocations allowed in kernel_launch)
__device__ float g_q[MTOT * CDIM];
__device__ float g_k[MTOT * CDIM];
__device__ float g_v[MTOT * CDIM];
__device__ float g_scr[MTOT * CDIM];

// ---------------------------------------------------------------------------
// SGEMM: C[m,n] = sum_k A[m,k] * B[n,k] (+ bias[n])
// Tile 128x128, BK=8, 256 threads, 8x8 per thread (split 64+64 sub-tiles).
// ---------------------------------------------------------------------------
__global__ __launch_bounds__(256) void sgemm128(
    const float* __restrict__ A, const float* __restrict__ B,
    const float* __restrict__ bias, float* __restrict__ C, int K)
{
    __shared__ float As[8][132];
    __shared__ float Bs[8][132];

    const int tid = threadIdx.x;
    const int tx  = tid & 15;   // 0..15 -> N
    const int ty  = tid >> 4;   // 0..15 -> M
    const int m0  = blockIdx.y * 128;
    const int n0  = blockIdx.x * 128;

    const int lrow = tid >> 1;        // 0..127
    const int lk4  = (tid & 1) * 4;   // 0 or 4

    float acc[8][8];
#pragma unroll
    for (int i = 0; i < 8; i++)
#pragma unroll
        for (int j = 0; j < 8; j++) acc[i][j] = 0.f;

    const float* Aptr = A + (size_t)(m0 + lrow) * K + lk4;
    const float* Bptr = B + (size_t)(n0 + lrow) * K + lk4;

    for (int k0 = 0; k0 < K; k0 += 8) {
        float4 av = *(const float4*)(Aptr + k0);
        float4 bv = *(const float4*)(Bptr + k0);
        As[lk4 + 0][lrow] = av.x; As[lk4 + 1][lrow] = av.y;
        As[lk4 + 2][lrow] = av.z; As[lk4 + 3][lrow] = av.w;
        Bs[lk4 + 0][lrow] = bv.x; Bs[lk4 + 1][lrow] = bv.y;
        Bs[lk4 + 2][lrow] = bv.z; Bs[lk4 + 3][lrow] = bv.w;
        __syncthreads();

#pragma unroll
        for (int kk = 0; kk < 8; kk++) {
            float4 a0 = *(const float4*)&As[kk][ty * 4];
            float4 a1 = *(const float4*)&As[kk][64 + ty * 4];
            float4 b0 = *(const float4*)&Bs[kk][tx * 4];
            float4 b1 = *(const float4*)&Bs[kk][64 + tx * 4];
            float a[8] = {a0.x, a0.y, a0.z, a0.w, a1.x, a1.y, a1.z, a1.w};
            float b[8] = {b0.x, b0.y, b0.z, b0.w, b1.x, b1.y, b1.z, b1.w};
#pragma unroll
            for (int i = 0; i < 8; i++)
#pragma unroll
                for (int j = 0; j < 8; j++)
                    acc[i][j] = fmaf(a[i], b[j], acc[i][j]);
        }
        __syncthreads();
    }

    // epilogue
    float bl0[4] = {0, 0, 0, 0}, bl1[4] = {0, 0, 0, 0};
    if (bias) {
#pragma unroll
        for (int j = 0; j < 4; j++) {
            bl0[j] = bias[n0 + tx * 4 + j];
            bl1[j] = bias[n0 + 64 + tx * 4 + j];
        }
    }
#pragma unroll
    for (int i = 0; i < 8; i++) {
        int r = m0 + ((i < 4) ? (ty * 4 + i) : (64 + ty * 4 + i - 4));
        float4 o0, o1;
        o0.x = acc[i][0] + bl0[0]; o0.y = acc[i][1] + bl0[1];
        o0.z = acc[i][2] + bl0[2]; o0.w = acc[i][3] + bl0[3];
        o1.x = acc[i][4] + bl1[0]; o1.y = acc[i][5] + bl1[1];
        o1.z = acc[i][6] + bl1[2]; o1.w = acc[i][7] + bl1[3];
        *(float4*)&C[(size_t)r * CDIM + n0 + tx * 4]      = o0;
        *(float4*)&C[(size_t)r * CDIM + n0 + 64 + tx * 4] = o1;
    }
}

// ---------------------------------------------------------------------------
// Per-pixel attention: one block (64 threads) per pixel.
// Writes the "scramble" layout directly:
//   scr[b, e*64 + n/64, (n%64)*8 + h] = out[b,n,h,e]
// The v = v+v doubling is folded into the output (l2norm is scale-invariant).
// ---------------------------------------------------------------------------
__global__ __launch_bounds__(64) void attn_kernel(
    const float* __restrict__ Q, const float* __restrict__ K,
    const float* __restrict__ V, float* __restrict__ scr)
{
    __shared__ float sq[8][64];
    __shared__ float sk[8][64];
    __shared__ float sv[8][64];
    __shared__ float rn[3][8];          // inverse l2 norms: q,k,v
    __shared__ float sA[8][8];          // head-mix attention
    __shared__ float sAttn[64][65];     // channel attention (padded)

    const int t   = threadIdx.x;        // 0..63
    const int pix = blockIdx.x;         // 0..16383
    const size_t base = (size_t)pix * CDIM;

    {
        float* pq = &sq[0][0]; float* pk = &sk[0][0]; float* pv = &sv[0][0];
#pragma unroll
        for (int i = t; i < 512; i += 64) {
            pq[i] = Q[base + i];
            pk[i] = K[base + i];
            pv[i] = V[base + i];
        }
    }
    __syncthreads();

    // inverse norms (threads 0..23)
    if (t < 24) {
        int which = t >> 3, h = t & 7;
        const float* p = (which == 0) ? &sq[h][0]
                       : (which == 1) ? &sk[h][0] : &sv[h][0];
        float s = 0.f;
#pragma unroll
        for (int d = 0; d < 64; d++) s = fmaf(p[d], p[d], s);
        rn[which][h] = 1.f / fmaxf(sqrtf(s), 1e-12f);
    }
    __syncthreads();

    // gram of normalized v: G[h][g]
    {
        int h = t >> 3, g = t & 7;
        float s = 0.f;
#pragma unroll
        for (int d = 0; d < 64; d++) s = fmaf(sv[h][d], sv[g][d], s);
        sA[h][g] = s * rn[2][h] * rn[2][g];
    }
    __syncthreads();

    // softmax over g (rows, threads 0..7)
    if (t < 8) {
        float m = -1e30f;
#pragma unroll
        for (int g = 0; g < 8; g++) m = fmaxf(m, sA[t][g]);
        float s = 0.f;
#pragma unroll
        for (int g = 0; g < 8; g++) { float e = __expf(sA[t][g] - m); sA[t][g] = e; s += e; }
        float inv = 1.f / s;
#pragma unroll
        for (int g = 0; g < 8; g++) sA[t][g] *= inv;
    }
    __syncthreads();

    // head mix: q' = A @ (q/|q|), k' = A @ (k/|k|)  (column-local, in place)
    {
        const int d = t;
        float qc[8], kc[8];
#pragma unroll
        for (int g = 0; g < 8; g++) {
            qc[g] = sq[g][d] * rn[0][g];
            kc[g] = sk[g][d] * rn[1][g];
        }
        float q2[8], k2[8];
#pragma unroll
        for (int h = 0; h < 8; h++) {
            float s1 = 0.f, s2 = 0.f;
#pragma unroll
            for (int g = 0; g < 8; g++) {
                s1 = fmaf(sA[h][g], qc[g], s1);
                s2 = fmaf(sA[h][g], kc[g], s2);
            }
            q2[h] = s1; k2[h] = s2;
        }
#pragma unroll
        for (int h = 0; h < 8; h++) { sq[h][d] = q2[h]; sk[h][d] = k2[h]; }
    }
    __syncthreads();

    // stage 2: attn[d][e] = softmax_e( sum_h k'[h,d] * q'[h,e] )
    {
        const int d = t;
        float kcol[8];
#pragma unroll
        for (int h = 0; h < 8; h++) kcol[h] = sk[h][d];
        float row[64];
        float m = -1e30f;
#pragma unroll
        for (int e = 0; e < 64; e++) {
            float s = 0.f;
#pragma unroll
            for (int h = 0; h < 8; h++) s = fmaf(kcol[h], sq[h][e], s);
            row[e] = s;
            m = fmaxf(m, s);
        }
        float sum = 0.f;
#pragma unroll
        for (int e = 0; e < 64; e++) { float ex = __expf(row[e] - m); row[e] = ex; sum += ex; }
        float inv = 1.f / sum;
#pragma unroll
        for (int e = 0; e < 64; e++) sAttn[d][e] = row[e] * inv;
    }
    __syncthreads();

    // out[h][e] = 2 * sum_d v[h,d] * attn[d,e]; scatter into scramble layout
    {
        const int e = t;
        float o[8] = {0, 0, 0, 0, 0, 0, 0, 0};
#pragma unroll
        for (int d = 0; d < 64; d++) {
            float a = sAttn[d][e];
#pragma unroll
            for (int h = 0; h < 8; h++) o[h] = fmaf(sv[h][d], a, o[h]);
        }
        const int b = pix >> 12;
        const int n = pix & 4095;
        const size_t rowi = (size_t)(b * 4096 + e * 64 + (n >> 6));
        float* dst = scr + rowi * CDIM + (n & 63) * 8;
#pragma unroll
        for (int h = 0; h < 8; h++) dst[h] = 2.f * o[h];
    }
}

// ---------------------------------------------------------------------------
extern "C" void kernel_launch(void* const* d_in, const int* in_sizes, int n_in,
                              void* d_out, int out_size)
{
    const float* x     = (const float*)d_in[0];
    const float* Wq    = (const float*)d_in[1];
    const float* Wk    = (const float*)d_in[2];
    const float* Wv    = (const float*)d_in[3];
    // d_in[4] = conv_w: dead in the reference (v overwritten), unused.
    const float* projw = (const float*)d_in[5];
    const float* projb = (const float*)d_in[6];
    float* out = (float*)d_out;

    float *gq, *gk, *gv, *gscr;
    cudaGetSymbolAddress((void**)&gq,   g_q);
    cudaGetSymbolAddress((void**)&gk,   g_k);
    cudaGetSymbolAddress((void**)&gv,   g_v);
    cudaGetSymbolAddress((void**)&gscr, g_scr);

    dim3 grid(CDIM / 128, MTOT / 128);   // (4, 128)
    sgemm128<<<grid, 256>>>(x, Wq, nullptr, gq, CDIM);
    sgemm128<<<grid, 256>>>(x, Wk, nullptr, gk, CDIM);
    sgemm128<<<grid, 256>>>(x, Wv, nullptr, gv, CDIM);

    attn_kernel<<<MTOT, 64>>>(gq, gk, gv, gscr);

    sgemm128<<<grid, 256>>>(gscr, projw, projb, out, CDIM);
}

// round 3
// speedup vs baseline: 1.7164x; 1.7164x over previous
#include <cuda_runtime.h>
#include <cuda_bf16.h>
#include <cuda_fp16.h>
#include <stdint.h>
#include <math.h>

#define MTOT 16384
#define CDIM 512

// ---------------------------------------------------------------------------
// Scratch (static __device__: no allocations allowed)
// ---------------------------------------------------------------------------
__device__ float g_q[MTOT * CDIM];
__device__ float g_k[MTOT * CDIM];
__device__ float g_v[MTOT * CDIM];
__device__ __nv_bfloat16 g_xhi[MTOT * CDIM];
__device__ __nv_bfloat16 g_xlo[MTOT * CDIM];
__device__ __nv_bfloat16 g_shi[MTOT * CDIM];
__device__ __nv_bfloat16 g_slo[MTOT * CDIM];
__device__ __nv_bfloat16 g_whi[4][CDIM * CDIM];  // Wq, Wk, Wv, proj_w
__device__ __nv_bfloat16 g_wlo[4][CDIM * CDIM];

// ---------------------------------------------------------------------------
// PTX helpers (arch-portable: ldmatrix / mma.sync / cp.async only)
// ---------------------------------------------------------------------------
__device__ __forceinline__ uint32_t smem_u32(const void* p) {
    uint32_t a;
    asm("{ .reg .u64 t; cvta.to.shared.u64 t, %1; cvt.u32.u64 %0, t; }"
        : "=r"(a) : "l"(p));
    return a;
}
__device__ __forceinline__ void ldm_x4(uint32_t* r, uint32_t addr) {
    asm volatile("ldmatrix.sync.aligned.m8n8.x4.shared.b16 {%0,%1,%2,%3}, [%4];"
                 : "=r"(r[0]), "=r"(r[1]), "=r"(r[2]), "=r"(r[3]) : "r"(addr));
}
__device__ __forceinline__ void mma_bf16(float* d, const uint32_t* a, const uint32_t* b) {
    asm volatile(
        "mma.sync.aligned.m16n8k16.row.col.f32.bf16.bf16.f32 "
        "{%0,%1,%2,%3}, {%4,%5,%6,%7}, {%8,%9}, {%0,%1,%2,%3};"
        : "+f"(d[0]), "+f"(d[1]), "+f"(d[2]), "+f"(d[3])
        : "r"(a[0]), "r"(a[1]), "r"(a[2]), "r"(a[3]), "r"(b[0]), "r"(b[1]));
}
__device__ __forceinline__ void cp_async16(uint32_t dst, const void* src) {
    asm volatile("cp.async.cg.shared.global [%0], [%1], 16;" :: "r"(dst), "l"(src));
}
#define CP_COMMIT() asm volatile("cp.async.commit_group;" ::: "memory")
#define CP_WAIT(N)  asm volatile("cp.async.wait_group %0;" :: "n"(N) : "memory")

// ---------------------------------------------------------------------------
// bf16x3 GEMM via mma.sync: C[m,n] = sum_k A[m,k]*B[n,k] (+bias)
// BM=128, BN=128, BK=32, 256 threads (8 warps, 2x4, warp tile 64x32),
// cp.async double-buffered. Padded pitch 40 bf16 -> conflict-free ldmatrix.
// ---------------------------------------------------------------------------
#define PITCH 40
#define TS (128 * PITCH)                 // bf16 elems per tile
#define NSTAGE_BYTES (4 * TS * 2)        // Ah, Al, Bh, Bl = 40960 B
#define GSMEM (2 * NSTAGE_BYTES)         // 81920 B

__global__ __launch_bounds__(256, 1)
void gemm_mma(const __nv_bfloat16* __restrict__ Ahi, const __nv_bfloat16* __restrict__ Alo,
              const __nv_bfloat16* __restrict__ Bhi, const __nv_bfloat16* __restrict__ Blo,
              const float* __restrict__ bias, float* __restrict__ C)
{
    extern __shared__ __align__(16) __nv_bfloat16 sm[];
    const int tid = threadIdx.x;
    const int wid = tid >> 5, L = tid & 31;
    const int m0 = blockIdx.y * 128;
    const int n0 = blockIdx.x * 128;
    const int wm = (wid >> 2) * 64;      // warp M offset
    const int wn = (wid & 3) * 32;       // warp N offset
    const uint32_t sb = smem_u32(sm);

    const __nv_bfloat16* srcs[4] = {
        Ahi + (size_t)m0 * CDIM, Alo + (size_t)m0 * CDIM,
        Bhi + (size_t)n0 * CDIM, Blo + (size_t)n0 * CDIM };

    float acc[4][4][4];
#pragma unroll
    for (int i = 0; i < 4; i++)
#pragma unroll
        for (int j = 0; j < 4; j++)
#pragma unroll
            for (int q = 0; q < 4; q++) acc[i][j][q] = 0.f;

    // per-lane ldmatrix addressing
    const int aRow = L & 15, aK = (L >> 4) * 8;
    const int bRowL = (L & 7) + ((L & 16) ? 8 : 0);
    const int bK = ((L >> 3) & 1) * 8;

    // stage loader: 4 tiles x 512 uint4, 256 threads -> 2 per tile
    auto load_stage = [&](int stage, int k0) {
#pragma unroll
        for (int t = 0; t < 4; t++) {
            const uint32_t tbase = sb + (uint32_t)(stage * 4 + t) * TS * 2;
#pragma unroll
            for (int half = 0; half < 2; half++) {
                int i = tid + half * 256;
                int r = i >> 2, c = i & 3;
                uint32_t dst = tbase + (uint32_t)(r * PITCH + c * 8) * 2;
                const __nv_bfloat16* src = srcs[t] + (size_t)r * CDIM + k0 + c * 8;
                cp_async16(dst, src);
            }
        }
    };

    load_stage(0, 0);
    CP_COMMIT();

    const int NIT = CDIM / 32;   // 16
    for (int s = 0; s < NIT; s++) {
        if (s + 1 < NIT) { load_stage((s + 1) & 1, (s + 1) * 32); CP_COMMIT(); CP_WAIT(1); }
        else             { CP_WAIT(0); }
        __syncthreads();

        const int buf = s & 1;
        const uint32_t bAh = sb + (uint32_t)(buf * 4 + 0) * TS * 2;
        const uint32_t bAl = sb + (uint32_t)(buf * 4 + 1) * TS * 2;
        const uint32_t bBh = sb + (uint32_t)(buf * 4 + 2) * TS * 2;
        const uint32_t bBl = sb + (uint32_t)(buf * 4 + 3) * TS * 2;

#pragma unroll
        for (int kk = 0; kk < 32; kk += 16) {
            uint32_t ah[4][4], al[4][4], bh[4][2], bl[4][2];
#pragma unroll
            for (int mi = 0; mi < 4; mi++) {
                uint32_t ro = (uint32_t)((wm + mi * 16 + aRow) * PITCH + kk + aK) * 2;
                ldm_x4(ah[mi], bAh + ro);
                ldm_x4(al[mi], bAl + ro);
            }
#pragma unroll
            for (int nb = 0; nb < 2; nb++) {
                uint32_t ro = (uint32_t)((wn + nb * 16 + bRowL) * PITCH + kk + bK) * 2;
                uint32_t th[4], tl[4];
                ldm_x4(th, bBh + ro);
                ldm_x4(tl, bBl + ro);
                bh[nb * 2][0] = th[0]; bh[nb * 2][1] = th[1];
                bh[nb * 2 + 1][0] = th[2]; bh[nb * 2 + 1][1] = th[3];
                bl[nb * 2][0] = tl[0]; bl[nb * 2][1] = tl[1];
                bl[nb * 2 + 1][0] = tl[2]; bl[nb * 2 + 1][1] = tl[3];
            }
#pragma unroll
            for (int mi = 0; mi < 4; mi++)
#pragma unroll
                for (int ni = 0; ni < 4; ni++) {
                    mma_bf16(acc[mi][ni], ah[mi], bh[ni]);
                    mma_bf16(acc[mi][ni], ah[mi], bl[ni]);
                    mma_bf16(acc[mi][ni], al[mi], bh[ni]);
                }
        }
        __syncthreads();
    }

    // epilogue
    const int cr = L >> 2, cc = (L & 3) * 2;
#pragma unroll
    for (int mi = 0; mi < 4; mi++) {
#pragma unroll
        for (int ni = 0; ni < 4; ni++) {
            int row = m0 + wm + mi * 16 + cr;
            int col = n0 + wn + ni * 8 + cc;
            float b0 = 0.f, b1 = 0.f;
            if (bias) { b0 = bias[col]; b1 = bias[col + 1]; }
            float2 o0 = make_float2(acc[mi][ni][0] + b0, acc[mi][ni][1] + b1);
            float2 o1 = make_float2(acc[mi][ni][2] + b0, acc[mi][ni][3] + b1);
            *(float2*)&C[(size_t)row * CDIM + col] = o0;
            *(float2*)&C[(size_t)(row + 8) * CDIM + col] = o1;
        }
    }
}

// ---------------------------------------------------------------------------
// fp32 -> (bf16 hi, bf16 lo) split, vectorized by 4
// ---------------------------------------------------------------------------
__global__ void cvt_hilo4(const float4* __restrict__ src,
                          uint2* __restrict__ hi, uint2* __restrict__ lo, int n4)
{
    int i = blockIdx.x * blockDim.x + threadIdx.x;
    if (i >= n4) return;
    float4 v = src[i];
    float f[4] = {v.x, v.y, v.z, v.w};
    union { uint2 u; __nv_bfloat16 b[4]; } H, L;
#pragma unroll
    for (int j = 0; j < 4; j++) {
        __nv_bfloat16 h = __float2bfloat16(f[j]);
        H.b[j] = h;
        L.b[j] = __float2bfloat16(f[j] - __bfloat162float(h));
    }
    hi[i] = H.u;
    lo[i] = L.u;
}

// ---------------------------------------------------------------------------
// Per-pixel attention (64 threads / pixel), no spills, fp16 score buffer.
// Writes bf16 hi/lo in the scramble layout:
//   scr[b, e*64 + n/64, (n%64)*8 + h] = 2 * out[b,n,h,e]
// ---------------------------------------------------------------------------
__global__ __launch_bounds__(64) void attn_kernel(
    const float* __restrict__ Q, const float* __restrict__ K,
    const float* __restrict__ V,
    __nv_bfloat16* __restrict__ scr_hi, __nv_bfloat16* __restrict__ scr_lo)
{
    __shared__ float sq[8][64];
    __shared__ float sk[8][64];
    __shared__ float sv[8][64];
    __shared__ float rn[3][8];
    __shared__ float sA[8][8];
    __shared__ __half sAttn[64][66];
    __shared__ float sInv[64];

    const int t   = threadIdx.x;
    const int pix = blockIdx.x;
    const size_t base = (size_t)pix * CDIM;

    {
        const float4* q4 = (const float4*)(Q + base);
        const float4* k4 = (const float4*)(K + base);
        const float4* v4 = (const float4*)(V + base);
        float4* sq4 = (float4*)&sq[0][0];
        float4* sk4 = (float4*)&sk[0][0];
        float4* sv4 = (float4*)&sv[0][0];
#pragma unroll
        for (int i = t; i < 128; i += 64) {
            sq4[i] = q4[i]; sk4[i] = k4[i]; sv4[i] = v4[i];
        }
    }
    __syncthreads();

    if (t < 24) {
        int which = t >> 3, h = t & 7;
        const float* p = (which == 0) ? &sq[h][0]
                       : (which == 1) ? &sk[h][0] : &sv[h][0];
        float s = 0.f;
#pragma unroll
        for (int d = 0; d < 64; d++) s = fmaf(p[d], p[d], s);
        rn[which][h] = 1.f / fmaxf(sqrtf(s), 1e-12f);
    }
    __syncthreads();

    // gram of normalized v
    {
        int h = t >> 3, g = t & 7;
        float s = 0.f;
#pragma unroll
        for (int d = 0; d < 64; d++) s = fmaf(sv[h][d], sv[g][d], s);
        sA[h][g] = s * rn[2][h] * rn[2][g];
    }
    __syncthreads();

    if (t < 8) {
        float m = -1e30f;
#pragma unroll
        for (int g = 0; g < 8; g++) m = fmaxf(m, sA[t][g]);
        float s = 0.f;
#pragma unroll
        for (int g = 0; g < 8; g++) { float e = __expf(sA[t][g] - m); sA[t][g] = e; s += e; }
        float inv = 1.f / s;
#pragma unroll
        for (int g = 0; g < 8; g++) sA[t][g] *= inv;
    }
    __syncthreads();

    // head mix (in place, column d = t)
    {
        const int d = t;
        float qc[8], kc[8];
#pragma unroll
        for (int g = 0; g < 8; g++) {
            qc[g] = sq[g][d] * rn[0][g];
            kc[g] = sk[g][d] * rn[1][g];
        }
        float q2[8], k2[8];
#pragma unroll
        for (int h = 0; h < 8; h++) {
            float s1 = 0.f, s2 = 0.f;
#pragma unroll
            for (int g = 0; g < 8; g++) {
                s1 = fmaf(sA[h][g], qc[g], s1);
                s2 = fmaf(sA[h][g], kc[g], s2);
            }
            q2[h] = s1; k2[h] = s2;
        }
#pragma unroll
        for (int h = 0; h < 8; h++) { sq[h][d] = q2[h]; sk[h][d] = k2[h]; }
    }
    __syncthreads();

    // stage 2: s[d][e] = k'_d . q'_e, softmax over e, exp stored fp16
    {
        const int d = t;
        float kcol[8];
#pragma unroll
        for (int h = 0; h < 8; h++) kcol[h] = sk[h][d];
        float row[8];  // process e in chunks of 8 to find max first? two-pass via recompute-free chunking
        float m = -1e30f;
        // pass 1: compute scores into sAttn as fp16 of raw score? need max first.
        // do: compute raw scores, track max, store raw score fp32-in-fp16 is lossy pre-exp.
        // Instead: chunked two-pass in registers of 8 at a time won't hold 64.
        // Use: store raw scores temporarily in fp16 (range small: |s|<=8), then exp pass.
#pragma unroll
        for (int e = 0; e < 64; e++) {
            float s = 0.f;
#pragma unroll
            for (int h = 0; h < 8; h++) s = fmaf(kcol[h], sq[h][e], s);
            sAttn[d][e] = __float2half(s);
            m = fmaxf(m, s);
        }
        float Z = 0.f;
#pragma unroll
        for (int e = 0; e < 64; e++) {
            float ex = __expf(__half2float(sAttn[d][e]) - m);
            sAttn[d][e] = __float2half(ex);
            Z += ex;
        }
        sInv[d] = 1.f / Z;
        (void)row;
    }
    __syncthreads();

    // out[h][e] = 2 * sum_d v[h,d] * attn[d,e]; scatter bf16 hi/lo scramble
    {
        const int e = t;
        float o[8] = {0, 0, 0, 0, 0, 0, 0, 0};
#pragma unroll
        for (int d = 0; d < 64; d++) {
            float a = __half2float(sAttn[d][e]) * sInv[d];
#pragma unroll
            for (int h = 0; h < 8; h++) o[h] = fmaf(sv[h][d], a, o[h]);
        }
        const int b = pix >> 12;
        const int n = pix & 4095;
        const size_t rowi = (size_t)(b * 4096 + e * 64 + (n >> 6));
        const size_t off  = rowi * CDIM + (n & 63) * 8;
        union { uint4 u; __nv_bfloat16 bb[8]; } H, L;
#pragma unroll
        for (int h = 0; h < 8; h++) {
            float v = 2.f * o[h];
            __nv_bfloat16 hb = __float2bfloat16(v);
            H.bb[h] = hb;
            L.bb[h] = __float2bfloat16(v - __bfloat162float(hb));
        }
        *(uint4*)(scr_hi + off) = H.u;
        *(uint4*)(scr_lo + off) = L.u;
    }
}

// ---------------------------------------------------------------------------
extern "C" void kernel_launch(void* const* d_in, const int* in_sizes, int n_in,
                              void* d_out, int out_size)
{
    const float* x     = (const float*)d_in[0];
    const float* Wq    = (const float*)d_in[1];
    const float* Wk    = (const float*)d_in[2];
    const float* Wv    = (const float*)d_in[3];
    // d_in[4] = conv_w: dead in the reference
    const float* projw = (const float*)d_in[5];
    const float* projb = (const float*)d_in[6];
    float* out = (float*)d_out;

    cudaFuncSetAttribute(gemm_mma, cudaFuncAttributeMaxDynamicSharedMemorySize, GSMEM);

    float *gq, *gk, *gv;
    __nv_bfloat16 *xhi, *xlo, *shi, *slo, *whi, *wlo;
    cudaGetSymbolAddress((void**)&gq,  g_q);
    cudaGetSymbolAddress((void**)&gk,  g_k);
    cudaGetSymbolAddress((void**)&gv,  g_v);
    cudaGetSymbolAddress((void**)&xhi, g_xhi);
    cudaGetSymbolAddress((void**)&xlo, g_xlo);
    cudaGetSymbolAddress((void**)&shi, g_shi);
    cudaGetSymbolAddress((void**)&slo, g_slo);
    cudaGetSymbolAddress((void**)&whi, g_whi);
    cudaGetSymbolAddress((void**)&wlo, g_wlo);

    const int WN = CDIM * CDIM;  // 262144

    cvt_hilo4<<<(MTOT * CDIM / 4 + 255) / 256, 256>>>(
        (const float4*)x, (uint2*)xhi, (uint2*)xlo, MTOT * CDIM / 4);
    cvt_hilo4<<<(WN / 4 + 255) / 256, 256>>>(
        (const float4*)Wq, (uint2*)(whi + 0 * WN), (uint2*)(wlo + 0 * WN), WN / 4);
    cvt_hilo4<<<(WN / 4 + 255) / 256, 256>>>(
        (const float4*)Wk, (uint2*)(whi + 1 * WN), (uint2*)(wlo + 1 * WN), WN / 4);
    cvt_hilo4<<<(WN / 4 + 255) / 256, 256>>>(
        (const float4*)Wv, (uint2*)(whi + 2 * WN), (uint2*)(wlo + 2 * WN), WN / 4);
    cvt_hilo4<<<(WN / 4 + 255) / 256, 256>>>(
        (const float4*)projw, (uint2*)(whi + 3 * WN), (uint2*)(wlo + 3 * WN), WN / 4);

    dim3 grid(CDIM / 128, MTOT / 128);  // (4, 128)
    gemm_mma<<<grid, 256, GSMEM>>>(xhi, xlo, whi + 0 * WN, wlo + 0 * WN, nullptr, gq);
    gemm_mma<<<grid, 256, GSMEM>>>(xhi, xlo, whi + 1 * WN, wlo + 1 * WN, nullptr, gk);
    gemm_mma<<<grid, 256, GSMEM>>>(xhi, xlo, whi + 2 * WN, wlo + 2 * WN, nullptr, gv);

    attn_kernel<<<MTOT, 64>>>(gq, gk, gv, shi, slo);

    gemm_mma<<<grid, 256, GSMEM>>>(shi, slo, whi + 3 * WN, wlo + 3 * WN, projb, out);
}

// round 4
// speedup vs baseline: 2.1974x; 1.2803x over previous
#include <cuda_runtime.h>
#include <cuda_fp16.h>
#include <stdint.h>
#include <math.h>

#define MTOT 16384
#define CDIM 512
#define NQKV 1536

// ---------------------------------------------------------------------------
// Scratch (static __device__: no allocations allowed)
// ---------------------------------------------------------------------------
__device__ __half g_xhi[MTOT * CDIM];
__device__ __half g_xlo[MTOT * CDIM];
__device__ float  g_qkv[(size_t)MTOT * NQKV];
__device__ __half g_shi[MTOT * CDIM];
__device__ __half g_slo[MTOT * CDIM];
__device__ __half g_w16[4 * CDIM * CDIM];   // rows: Wq(0-511) Wk Wv proj

// ---------------------------------------------------------------------------
// PTX helpers (arch-portable)
// ---------------------------------------------------------------------------
__device__ __forceinline__ uint32_t smem_u32(const void* p) {
    uint32_t a;
    asm("{ .reg .u64 t; cvta.to.shared.u64 t, %1; cvt.u32.u64 %0, t; }"
        : "=r"(a) : "l"(p));
    return a;
}
__device__ __forceinline__ void ldm_x4(uint32_t* r, uint32_t addr) {
    asm volatile("ldmatrix.sync.aligned.m8n8.x4.shared.b16 {%0,%1,%2,%3}, [%4];"
                 : "=r"(r[0]), "=r"(r[1]), "=r"(r[2]), "=r"(r[3]) : "r"(addr));
}
__device__ __forceinline__ void mma_f16(float* d, const uint32_t* a, const uint32_t* b) {
    asm volatile(
        "mma.sync.aligned.m16n8k16.row.col.f32.f16.f16.f32 "
        "{%0,%1,%2,%3}, {%4,%5,%6,%7}, {%8,%9}, {%0,%1,%2,%3};"
        : "+f"(d[0]), "+f"(d[1]), "+f"(d[2]), "+f"(d[3])
        : "r"(a[0]), "r"(a[1]), "r"(a[2]), "r"(a[3]), "r"(b[0]), "r"(b[1]));
}
__device__ __forceinline__ void cp_async16(uint32_t dst, const void* src) {
    asm volatile("cp.async.cg.shared.global [%0], [%1], 16;" :: "r"(dst), "l"(src));
}
#define CP_COMMIT() asm volatile("cp.async.commit_group;" ::: "memory")
#define CP_WAIT(N)  asm volatile("cp.async.wait_group %0;" :: "n"(N) : "memory")

// ---------------------------------------------------------------------------
// 2-term fp16 GEMM: C[m,n] = sum_k (Ahi+Alo)[m,k] * B[n,k] (+bias)
// BM=256, BN=128, BK=32, 512 threads (16 warps, 4x4, warp tile 64x32),
// 3-stage cp.async pipeline. Pitch 40 halfs -> conflict-free ldmatrix.
// ---------------------------------------------------------------------------
#define PITCH 40
#define SH ((256 + 256 + 128) * PITCH)      // halfs per stage = 25600
#define OFF_AL (256 * PITCH)
#define OFF_B  (512 * PITCH)
#define GSMEM (3 * SH * 2)                  // 153600 B

__global__ __launch_bounds__(512, 1)
void gemm_2t(const __half* __restrict__ Ahi, const __half* __restrict__ Alo,
             const __half* __restrict__ B, const float* __restrict__ bias,
             float* __restrict__ C, int ldc)
{
    extern __shared__ __align__(16) __half sm[];
    const int tid = threadIdx.x;
    const int wid = tid >> 5, L = tid & 31;
    const int m0 = blockIdx.y * 256;
    const int n0 = blockIdx.x * 128;
    const int wm = (wid >> 2) * 64;
    const int wn = (wid & 3) * 32;
    const uint32_t sb = smem_u32(sm);

    const __half* Ah = Ahi + (size_t)m0 * CDIM;
    const __half* Al = Alo + (size_t)m0 * CDIM;
    const __half* Bt = B + (size_t)n0 * CDIM;

    float acc[4][4][4];
#pragma unroll
    for (int i = 0; i < 4; i++)
#pragma unroll
        for (int j = 0; j < 4; j++)
#pragma unroll
            for (int q = 0; q < 4; q++) acc[i][j][q] = 0.f;

    const int aRow = L & 15, aK = (L >> 4) * 8;
    const int bRowL = (L & 7) + ((L & 16) ? 8 : 0);
    const int bK = ((L >> 3) & 1) * 8;

    const int lr = tid >> 2, lc = tid & 3;   // loader: row / 16B-chunk

    auto load_stage = [&](int stage, int k0) {
        const uint32_t s0 = sb + (uint32_t)stage * SH * 2;
        uint32_t doff = (uint32_t)(lr * PITCH + lc * 8) * 2;
        uint32_t doff2 = (uint32_t)((lr + 128) * PITCH + lc * 8) * 2;
        size_t goff = (size_t)lr * CDIM + k0 + lc * 8;
        size_t goff2 = goff + (size_t)128 * CDIM;
        cp_async16(s0 + doff,                 Ah + goff);
        cp_async16(s0 + doff2,                Ah + goff2);
        cp_async16(s0 + OFF_AL * 2 + doff,    Al + goff);
        cp_async16(s0 + OFF_AL * 2 + doff2,   Al + goff2);
        cp_async16(s0 + OFF_B * 2 + doff,     Bt + goff);
    };

    load_stage(0, 0); CP_COMMIT();
    load_stage(1, 32); CP_COMMIT();

    const int NIT = CDIM / 32;   // 16
    for (int s = 0; s < NIT; s++) {
        CP_WAIT(1);
        __syncthreads();
        if (s + 2 < NIT) load_stage((s + 2) % 3, (s + 2) * 32);
        CP_COMMIT();

        const uint32_t pAh = sb + (uint32_t)(s % 3) * SH * 2;
        const uint32_t pAl = pAh + OFF_AL * 2;
        const uint32_t pB  = pAh + OFF_B * 2;

#pragma unroll
        for (int kk = 0; kk < 32; kk += 16) {
            uint32_t ah[4][4], al[4][4], bh[4][2];
#pragma unroll
            for (int mi = 0; mi < 4; mi++) {
                uint32_t ro = (uint32_t)((wm + mi * 16 + aRow) * PITCH + kk + aK) * 2;
                ldm_x4(ah[mi], pAh + ro);
                ldm_x4(al[mi], pAl + ro);
            }
#pragma unroll
            for (int nb = 0; nb < 2; nb++) {
                uint32_t ro = (uint32_t)((wn + nb * 16 + bRowL) * PITCH + kk + bK) * 2;
                uint32_t th[4];
                ldm_x4(th, pB + ro);
                bh[nb * 2][0] = th[0]; bh[nb * 2][1] = th[1];
                bh[nb * 2 + 1][0] = th[2]; bh[nb * 2 + 1][1] = th[3];
            }
#pragma unroll
            for (int mi = 0; mi < 4; mi++)
#pragma unroll
                for (int ni = 0; ni < 4; ni++) {
                    mma_f16(acc[mi][ni], ah[mi], bh[ni]);
                    mma_f16(acc[mi][ni], al[mi], bh[ni]);
                }
        }
        __syncthreads();
    }

    const int cr = L >> 2, cc = (L & 3) * 2;
#pragma unroll
    for (int mi = 0; mi < 4; mi++) {
#pragma unroll
        for (int ni = 0; ni < 4; ni++) {
            int row = m0 + wm + mi * 16 + cr;
            int col = n0 + wn + ni * 8 + cc;
            float b0 = 0.f, b1 = 0.f;
            if (bias) { b0 = bias[col]; b1 = bias[col + 1]; }
            float2 o0 = make_float2(acc[mi][ni][0] + b0, acc[mi][ni][1] + b1);
            float2 o1 = make_float2(acc[mi][ni][2] + b0, acc[mi][ni][3] + b1);
            *(float2*)&C[(size_t)row * ldc + col] = o0;
            *(float2*)&C[(size_t)(row + 8) * ldc + col] = o1;
        }
    }
}

// ---------------------------------------------------------------------------
// fp32 -> fp16 hi/lo split (activations)
// ---------------------------------------------------------------------------
__global__ void cvt_x(const float4* __restrict__ src,
                      uint2* __restrict__ hi, uint2* __restrict__ lo, int n4)
{
    int i = blockIdx.x * blockDim.x + threadIdx.x;
    if (i >= n4) return;
    float4 v = src[i];
    float f[4] = {v.x, v.y, v.z, v.w};
    union { uint2 u; __half b[4]; } H, L;
#pragma unroll
    for (int j = 0; j < 4; j++) {
        __half h = __float2half(f[j]);
        H.b[j] = h;
        L.b[j] = __float2half(f[j] - __half2float(h));
    }
    hi[i] = H.u;
    lo[i] = L.u;
}

// fp32 weights -> plain fp16, all 4 matrices in one launch (blockIdx.y selects)
__global__ void cvt_w(const float4* __restrict__ w0, const float4* __restrict__ w1,
                      const float4* __restrict__ w2, const float4* __restrict__ w3,
                      uint2* __restrict__ dst)
{
    int wsel = blockIdx.y;
    const float4* src = (wsel == 0) ? w0 : (wsel == 1) ? w1 : (wsel == 2) ? w2 : w3;
    int i = blockIdx.x * blockDim.x + threadIdx.x;   // 0..65535
    float4 v = src[i];
    union { uint2 u; __half b[4]; } H;
    H.b[0] = __float2half(v.x); H.b[1] = __float2half(v.y);
    H.b[2] = __float2half(v.z); H.b[3] = __float2half(v.w);
    dst[(size_t)wsel * 65536 + i] = H.u;
}

// ---------------------------------------------------------------------------
// Per-pixel attention (64 threads / pixel).
// Reads fused q|k|v row from g_qkv (row stride 1536).
// Transposed shared layouts -> float4 broadcast reads in hot loops.
// k' never leaves registers (head-mix thread d == stage-2 thread d).
// 1/Z and the v+v doubling folded into svT.
// scr[b, e*64 + n/64, (n%64)*8 + h] = 2*out[b,n,h,e], stored fp16 hi/lo.
// ---------------------------------------------------------------------------
__global__ __launch_bounds__(64) void attn_kernel(
    const float* __restrict__ QKV,
    __half* __restrict__ scr_hi, __half* __restrict__ scr_lo)
{
    __shared__ float sq[8][64];
    __shared__ float sk[8][64];
    __shared__ float sv[8][64];
    __shared__ float rn[3][8];
    __shared__ float sA[8][8];
    __shared__ __align__(16) float sqT[64][8];   // q'[h][e] at sqT[e][h]
    __shared__ __align__(16) float svT[64][8];   // 2*inv[d]*v[h][d] at svT[d][h]
    __shared__ __half sT[64][66];                // exp(S[d][e]) at sT[e][d]
    __shared__ float sInv[64];

    const int t   = threadIdx.x;
    const int pix = blockIdx.x;
    const size_t b4 = (size_t)pix * (NQKV / 4);

    {
        const float4* r4 = (const float4*)QKV + b4;
        float4* sq4 = (float4*)&sq[0][0];
        float4* sk4 = (float4*)&sk[0][0];
        float4* sv4 = (float4*)&sv[0][0];
#pragma unroll
        for (int i = t; i < 128; i += 64) {
            sq4[i] = r4[i];
            sk4[i] = r4[128 + i];
            sv4[i] = r4[256 + i];
        }
    }
    __syncthreads();

    if (t < 24) {
        int which = t >> 3, h = t & 7;
        const float* p = (which == 0) ? &sq[h][0]
                       : (which == 1) ? &sk[h][0] : &sv[h][0];
        float s = 0.f;
#pragma unroll
        for (int d = 0; d < 64; d++) s = fmaf(p[d], p[d], s);
        rn[which][h] = 1.f / fmaxf(sqrtf(s), 1e-12f);
    }
    __syncthreads();

    // gram of normalized v
    {
        int h = t >> 3, g = t & 7;
        float s = 0.f;
#pragma unroll
        for (int d = 0; d < 64; d++) s = fmaf(sv[h][d], sv[g][d], s);
        sA[h][g] = s * rn[2][h] * rn[2][g];
    }
    __syncthreads();

    if (t < 8) {
        float m = -1e30f;
#pragma unroll
        for (int g = 0; g < 8; g++) m = fmaxf(m, sA[t][g]);
        float s = 0.f;
#pragma unroll
        for (int g = 0; g < 8; g++) { float e = __expf(sA[t][g] - m); sA[t][g] = e; s += e; }
        float inv = 1.f / s;
#pragma unroll
        for (int g = 0; g < 8; g++) sA[t][g] *= inv;
    }
    __syncthreads();

    // head mix, thread d; k' kept in registers for stage 2
    float k2[8];
    {
        const int d = t;
        float qc[8], kc[8];
#pragma unroll
        for (int g = 0; g < 8; g++) {
            qc[g] = sq[g][d] * rn[0][g];
            kc[g] = sk[g][d] * rn[1][g];
        }
#pragma unroll
        for (int h = 0; h < 8; h++) {
            float s1 = 0.f, s2 = 0.f;
#pragma unroll
            for (int g = 0; g < 8; g++) {
                s1 = fmaf(sA[h][g], qc[g], s1);
                s2 = fmaf(sA[h][g], kc[g], s2);
            }
            sqT[d][h] = s1;
            k2[h] = s2;
        }
    }
    __syncthreads();

    // stage 2: S[d][e] = k'_d . q'_e stored at sT[e][d]; softmax over e
    {
        const int d = t;
        float m = -1e30f;
#pragma unroll
        for (int e = 0; e < 64; e++) {
            float4 qa = *(const float4*)&sqT[e][0];
            float4 qb = *(const float4*)&sqT[e][4];
            float s = k2[0] * qa.x;
            s = fmaf(k2[1], qa.y, s);
            s = fmaf(k2[2], qa.z, s);
            s = fmaf(k2[3], qa.w, s);
            s = fmaf(k2[4], qb.x, s);
            s = fmaf(k2[5], qb.y, s);
            s = fmaf(k2[6], qb.z, s);
            s = fmaf(k2[7], qb.w, s);
            sT[e][d] = __float2half(s);
            m = fmaxf(m, s);
        }
        float Z = 0.f;
#pragma unroll
        for (int e = 0; e < 64; e++) {
            float ex = __expf(__half2float(sT[e][d]) - m);
            sT[e][d] = __float2half(ex);
            Z += ex;
        }
        sInv[t] = 1.f / Z;
    }
    __syncthreads();

    // svT[d][h] = 2 * inv[d] * v[h][d]
    {
        const int d = t;
        float sc = 2.f * sInv[d];
#pragma unroll
        for (int h = 0; h < 8; h++) svT[d][h] = sv[h][d] * sc;
    }
    __syncthreads();

    // out[h][e] = sum_d sT[e][d] * svT[d][h]; scatter fp16 hi/lo scramble
    {
        const int e = t;
        float o[8] = {0, 0, 0, 0, 0, 0, 0, 0};
#pragma unroll
        for (int d = 0; d < 64; d++) {
            float a = __half2float(sT[e][d]);
            float4 va = *(const float4*)&svT[d][0];
            float4 vb = *(const float4*)&svT[d][4];
            o[0] = fmaf(a, va.x, o[0]);
            o[1] = fmaf(a, va.y, o[1]);
            o[2] = fmaf(a, va.z, o[2]);
            o[3] = fmaf(a, va.w, o[3]);
            o[4] = fmaf(a, vb.x, o[4]);
            o[5] = fmaf(a, vb.y, o[5]);
            o[6] = fmaf(a, vb.z, o[6]);
            o[7] = fmaf(a, vb.w, o[7]);
        }
        const int b = pix >> 12;
        const int n = pix & 4095;
        const size_t rowi = (size_t)(b * 4096 + e * 64 + (n >> 6));
        const size_t off  = rowi * CDIM + (n & 63) * 8;
        union { uint2 u; __half bb[4]; } H0, H1, L0, L1;
#pragma unroll
        for (int h = 0; h < 4; h++) {
            __half hb = __float2half(o[h]);
            H0.bb[h] = hb;
            L0.bb[h] = __float2half(o[h] - __half2float(hb));
        }
#pragma unroll
        for (int h = 0; h < 4; h++) {
            __half hb = __float2half(o[h + 4]);
            H1.bb[h] = hb;
            L1.bb[h] = __float2half(o[h + 4] - __half2float(hb));
        }
        *(uint2*)(scr_hi + off)     = H0.u;
        *(uint2*)(scr_hi + off + 4) = H1.u;
        *(uint2*)(scr_lo + off)     = L0.u;
        *(uint2*)(scr_lo + off + 4) = L1.u;
    }
}

// ---------------------------------------------------------------------------
extern "C" void kernel_launch(void* const* d_in, const int* in_sizes, int n_in,
                              void* d_out, int out_size)
{
    const float* x     = (const float*)d_in[0];
    const float* Wq    = (const float*)d_in[1];
    const float* Wk    = (const float*)d_in[2];
    const float* Wv    = (const float*)d_in[3];
    // d_in[4] = conv_w: dead in the reference
    const float* projw = (const float*)d_in[5];
    const float* projb = (const float*)d_in[6];
    float* out = (float*)d_out;

    cudaFuncSetAttribute(gemm_2t, cudaFuncAttributeMaxDynamicSharedMemorySize, GSMEM);

    __half *xhi, *xlo, *shi, *slo, *w16;
    float* qkv;
    cudaGetSymbolAddress((void**)&xhi, g_xhi);
    cudaGetSymbolAddress((void**)&xlo, g_xlo);
    cudaGetSymbolAddress((void**)&shi, g_shi);
    cudaGetSymbolAddress((void**)&slo, g_slo);
    cudaGetSymbolAddress((void**)&w16, g_w16);
    cudaGetSymbolAddress((void**)&qkv, g_qkv);

    // activation split + weight converts
    cvt_x<<<MTOT * CDIM / 4 / 256, 256>>>(
        (const float4*)x, (uint2*)xhi, (uint2*)xlo, MTOT * CDIM / 4);
    cvt_w<<<dim3(256, 4), 256>>>(
        (const float4*)Wq, (const float4*)Wk, (const float4*)Wv,
        (const float4*)projw, (uint2*)w16);

    // fused QKV GEMM: [16384,512] x [1536,512]^T -> [16384,1536]
    gemm_2t<<<dim3(NQKV / 128, MTOT / 256), 512, GSMEM>>>(
        xhi, xlo, w16, nullptr, qkv, NQKV);

    attn_kernel<<<MTOT, 64>>>(qkv, shi, slo);

    // proj GEMM: [16384,512] x [512,512]^T -> out
    gemm_2t<<<dim3(CDIM / 128, MTOT / 256), 512, GSMEM>>>(
        shi, slo, w16 + 3 * CDIM * CDIM, projb, out, CDIM);
}

// round 5
// speedup vs baseline: 2.6348x; 1.1990x over previous
#include <cuda_runtime.h>
#include <cuda_fp16.h>
#include <stdint.h>
#include <math.h>

#define MTOT 16384
#define CDIM 512
#define NQKV 1536

// ---------------------------------------------------------------------------
// Scratch (static __device__: no allocations allowed)
// ---------------------------------------------------------------------------
__device__ __half g_x16[MTOT * CDIM];
__device__ float  g_qkv[(size_t)MTOT * NQKV];
__device__ __half g_s16[MTOT * CDIM];
__device__ __half g_w16[4 * CDIM * CDIM];   // Wq, Wk, Wv, proj

// ---------------------------------------------------------------------------
// PTX helpers (arch-portable)
// ---------------------------------------------------------------------------
__device__ __forceinline__ uint32_t smem_u32(const void* p) {
    uint32_t a;
    asm("{ .reg .u64 t; cvta.to.shared.u64 t, %1; cvt.u32.u64 %0, t; }"
        : "=r"(a) : "l"(p));
    return a;
}
__device__ __forceinline__ void ldm_x4(uint32_t* r, uint32_t addr) {
    asm volatile("ldmatrix.sync.aligned.m8n8.x4.shared.b16 {%0,%1,%2,%3}, [%4];"
                 : "=r"(r[0]), "=r"(r[1]), "=r"(r[2]), "=r"(r[3]) : "r"(addr));
}
__device__ __forceinline__ void mma_f16(float* d, const uint32_t* a, const uint32_t* b) {
    asm volatile(
        "mma.sync.aligned.m16n8k16.row.col.f32.f16.f16.f32 "
        "{%0,%1,%2,%3}, {%4,%5,%6,%7}, {%8,%9}, {%0,%1,%2,%3};"
        : "+f"(d[0]), "+f"(d[1]), "+f"(d[2]), "+f"(d[3])
        : "r"(a[0]), "r"(a[1]), "r"(a[2]), "r"(a[3]), "r"(b[0]), "r"(b[1]));
}
__device__ __forceinline__ void cp_async16(uint32_t dst, const void* src) {
    asm volatile("cp.async.cg.shared.global [%0], [%1], 16;" :: "r"(dst), "l"(src));
}
#define CP_COMMIT() asm volatile("cp.async.commit_group;" ::: "memory")
#define CP_WAIT(N)  asm volatile("cp.async.wait_group %0;" :: "n"(N) : "memory")

// ---------------------------------------------------------------------------
// fp16 GEMM: C[m,n] = sum_k A[m,k] * B[n,k] (+bias)
// BM=256, BN=128, BK=32, 512 threads (16 warps, warp tile 64x32),
// 4-stage cp.async pipeline. Pitch 40 halfs -> conflict-free ldmatrix.
// ---------------------------------------------------------------------------
#define PITCH 40
#define SH ((256 + 128) * PITCH)            // halfs per stage = 15360
#define OFF_B (256 * PITCH)
#define NSTG 4
#define GSMEM (NSTG * SH * 2)               // 122880 B

__global__ __launch_bounds__(512, 1)
void gemm_f16(const __half* __restrict__ A, const __half* __restrict__ B,
              const float* __restrict__ bias, float* __restrict__ C, int ldc)
{
    extern __shared__ __align__(16) __half sm[];
    const int tid = threadIdx.x;
    const int wid = tid >> 5, L = tid & 31;
    const int m0 = blockIdx.y * 256;
    const int n0 = blockIdx.x * 128;
    const int wm = (wid >> 2) * 64;
    const int wn = (wid & 3) * 32;
    const uint32_t sb = smem_u32(sm);

    const __half* Ab = A + (size_t)m0 * CDIM;
    const __half* Bb = B + (size_t)n0 * CDIM;

    float acc[4][4][4];
#pragma unroll
    for (int i = 0; i < 4; i++)
#pragma unroll
        for (int j = 0; j < 4; j++)
#pragma unroll
            for (int q = 0; q < 4; q++) acc[i][j][q] = 0.f;

    const int aRow = L & 15, aK = (L >> 4) * 8;
    const int bRowL = (L & 7) + ((L & 16) ? 8 : 0);
    const int bK = ((L >> 3) & 1) * 8;

    const int lr = tid >> 2, lc = tid & 3;

    auto load_stage = [&](int stage, int k0) {
        const uint32_t s0 = sb + (uint32_t)stage * SH * 2;
        uint32_t doff  = (uint32_t)(lr * PITCH + lc * 8) * 2;
        uint32_t doff2 = (uint32_t)((lr + 128) * PITCH + lc * 8) * 2;
        size_t goff  = (size_t)lr * CDIM + k0 + lc * 8;
        cp_async16(s0 + doff,              Ab + goff);
        cp_async16(s0 + doff2,             Ab + goff + (size_t)128 * CDIM);
        cp_async16(s0 + OFF_B * 2 + doff,  Bb + goff);
    };

    load_stage(0, 0);  CP_COMMIT();
    load_stage(1, 32); CP_COMMIT();
    load_stage(2, 64); CP_COMMIT();

    const int NIT = CDIM / 32;   // 16
    for (int s = 0; s < NIT; s++) {
        CP_WAIT(2);
        __syncthreads();
        if (s + 3 < NIT) load_stage((s + 3) & 3, (s + 3) * 32);
        CP_COMMIT();

        const uint32_t pA = sb + (uint32_t)(s & 3) * SH * 2;
        const uint32_t pB = pA + OFF_B * 2;

#pragma unroll
        for (int kk = 0; kk < 32; kk += 16) {
            uint32_t ah[4][4], bh[4][2];
#pragma unroll
            for (int mi = 0; mi < 4; mi++) {
                uint32_t ro = (uint32_t)((wm + mi * 16 + aRow) * PITCH + kk + aK) * 2;
                ldm_x4(ah[mi], pA + ro);
            }
#pragma unroll
            for (int nb = 0; nb < 2; nb++) {
                uint32_t ro = (uint32_t)((wn + nb * 16 + bRowL) * PITCH + kk + bK) * 2;
                uint32_t th[4];
                ldm_x4(th, pB + ro);
                bh[nb * 2][0] = th[0];     bh[nb * 2][1] = th[1];
                bh[nb * 2 + 1][0] = th[2]; bh[nb * 2 + 1][1] = th[3];
            }
#pragma unroll
            for (int mi = 0; mi < 4; mi++)
#pragma unroll
                for (int ni = 0; ni < 4; ni++)
                    mma_f16(acc[mi][ni], ah[mi], bh[ni]);
        }
        __syncthreads();
    }

    const int cr = L >> 2, cc = (L & 3) * 2;
#pragma unroll
    for (int mi = 0; mi < 4; mi++) {
#pragma unroll
        for (int ni = 0; ni < 4; ni++) {
            int row = m0 + wm + mi * 16 + cr;
            int col = n0 + wn + ni * 8 + cc;
            float b0 = 0.f, b1 = 0.f;
            if (bias) { b0 = bias[col]; b1 = bias[col + 1]; }
            float2 o0 = make_float2(acc[mi][ni][0] + b0, acc[mi][ni][1] + b1);
            float2 o1 = make_float2(acc[mi][ni][2] + b0, acc[mi][ni][3] + b1);
            *(float2*)&C[(size_t)row * ldc + col] = o0;
            *(float2*)&C[(size_t)(row + 8) * ldc + col] = o1;
        }
    }
}

// ---------------------------------------------------------------------------
// fp32 -> fp16 converts
// ---------------------------------------------------------------------------
__global__ void cvt_x(const float4* __restrict__ src, uint2* __restrict__ dst, int n4)
{
    int i = blockIdx.x * blockDim.x + threadIdx.x;
    if (i >= n4) return;
    float4 v = src[i];
    union { uint2 u; __half b[4]; } H;
    H.b[0] = __float2half(v.x); H.b[1] = __float2half(v.y);
    H.b[2] = __float2half(v.z); H.b[3] = __float2half(v.w);
    dst[i] = H.u;
}

__global__ void cvt_w(const float4* __restrict__ w0, const float4* __restrict__ w1,
                      const float4* __restrict__ w2, const float4* __restrict__ w3,
                      uint2* __restrict__ dst)
{
    int wsel = blockIdx.y;
    const float4* src = (wsel == 0) ? w0 : (wsel == 1) ? w1 : (wsel == 2) ? w2 : w3;
    int i = blockIdx.x * blockDim.x + threadIdx.x;
    float4 v = src[i];
    union { uint2 u; __half b[4]; } H;
    H.b[0] = __float2half(v.x); H.b[1] = __float2half(v.y);
    H.b[2] = __float2half(v.z); H.b[3] = __float2half(v.w);
    dst[(size_t)wsel * 65536 + i] = H.u;
}

// ---------------------------------------------------------------------------
// Per-pixel attention: 128 threads / pixel.
// Pairwise split across thread pairs (shfl-combined): stage-2 splits the e
// range, output splits the d range. No max-subtraction in stage-2 softmax:
// q', k' are convex combos of unit vectors => |score| <= 1, exp safe, and
// softmax is shift-invariant (exact). 1/Z and the v+v doubling fold into svT.
// scr[b, e*64 + n/64, (n%64)*8 + h] = 2*out[b,n,h,e], fp16.
// ---------------------------------------------------------------------------
#define STP 72   // sT pitch in halfs (144B: 16B-aligned rows)

__global__ __launch_bounds__(128) void attn_kernel(
    const float* __restrict__ QKV, __half* __restrict__ scr)
{
    __shared__ float sq[8][64];
    __shared__ float sk[8][64];
    __shared__ float sv[8][64];
    __shared__ float rn[3][8];
    __shared__ float sA[8][8];
    __shared__ __align__(16) float sqT[64][8];     // q'[h][e] at sqT[e][h]
    __shared__ __align__(16) float svT[64][8];     // 2*inv[d]*v[h][d] at svT[d][h]
    __shared__ __align__(16) __half sT[64][STP];   // exp(S[d][e]) at sT[e][d]

    const int t   = threadIdx.x;
    const int pix = blockIdx.x;

    {
        const float4* r4 = (const float4*)QKV + (size_t)pix * (NQKV / 4);
        ((float4*)&sq[0][0])[t & 127] = r4[t];
        // t in 0..127 loads: sq part with first 128, etc. Explicit:
    }
    // redo load cleanly (one iteration covers 384 float4 with 3 per thread)
    {
        const float4* r4 = (const float4*)QKV + (size_t)pix * (NQKV / 4);
        float4* sq4 = (float4*)&sq[0][0];
        float4* sk4 = (float4*)&sk[0][0];
        float4* sv4 = (float4*)&sv[0][0];
        sq4[t] = r4[t];
        sk4[t] = r4[128 + t];
        sv4[t] = r4[256 + t];
    }
    __syncthreads();

    if (t < 24) {
        int which = t >> 3, h = t & 7;
        const float* p = (which == 0) ? &sq[h][0]
                       : (which == 1) ? &sk[h][0] : &sv[h][0];
        float s = 0.f;
#pragma unroll
        for (int d = 0; d < 64; d++) s = fmaf(p[d], p[d], s);
        rn[which][h] = 1.f / fmaxf(sqrtf(s), 1e-12f);
    }
    __syncthreads();

    // gram of normalized v (threads 0..63)
    if (t < 64) {
        int h = t >> 3, g = t & 7;
        float s = 0.f;
#pragma unroll
        for (int d = 0; d < 64; d++) s = fmaf(sv[h][d], sv[g][d], s);
        sA[h][g] = s * rn[2][h] * rn[2][g];
    }
    __syncthreads();

    if (t < 8) {
        float m = -1e30f;
#pragma unroll
        for (int g = 0; g < 8; g++) m = fmaxf(m, sA[t][g]);
        float s = 0.f;
#pragma unroll
        for (int g = 0; g < 8; g++) { float e = __expf(sA[t][g] - m); sA[t][g] = e; s += e; }
        float inv = 1.f / s;
#pragma unroll
        for (int g = 0; g < 8; g++) sA[t][g] *= inv;
    }
    __syncthreads();

    // head mix: thread pair (d = t>>1, sel = t&1). Both compute k' (kept in
    // regs for stage 2); sel==0 additionally computes q' -> sqT.
    float k2[8];
    {
        const int d = t >> 1, sel = t & 1;
        float kc[8];
#pragma unroll
        for (int g = 0; g < 8; g++) kc[g] = sk[g][d] * rn[1][g];
#pragma unroll
        for (int h = 0; h < 8; h++) {
            float s2 = 0.f;
#pragma unroll
            for (int g = 0; g < 8; g++) s2 = fmaf(sA[h][g], kc[g], s2);
            k2[h] = s2;
        }
        if (sel == 0) {
            float qc[8];
#pragma unroll
            for (int g = 0; g < 8; g++) qc[g] = sq[g][d] * rn[0][g];
#pragma unroll
            for (int h = 0; h < 8; h++) {
                float s1 = 0.f;
#pragma unroll
                for (int g = 0; g < 8; g++) s1 = fmaf(sA[h][g], qc[g], s1);
                sqT[d][h] = s1;
            }
        }
    }
    __syncthreads();

    // stage 2: thread (d = t>>1, eh = t&1) handles 32 e's. Single pass:
    // exp without max (|S|<=1), Z combined across the pair via shfl.
    {
        const int d = t >> 1, eh = t & 1, e0 = eh << 5;
        float Z = 0.f;
#pragma unroll
        for (int i = 0; i < 32; i++) {
            const int e = e0 + i;
            float4 qa = *(const float4*)&sqT[e][0];
            float4 qb = *(const float4*)&sqT[e][4];
            float s = k2[0] * qa.x;
            s = fmaf(k2[1], qa.y, s);
            s = fmaf(k2[2], qa.z, s);
            s = fmaf(k2[3], qa.w, s);
            s = fmaf(k2[4], qb.x, s);
            s = fmaf(k2[5], qb.y, s);
            s = fmaf(k2[6], qb.z, s);
            s = fmaf(k2[7], qb.w, s);
            float ex = __expf(s);
            Z += ex;
            sT[e][d] = __float2half(ex);
        }
        Z += __shfl_xor_sync(0xffffffffu, Z, 1);
        // svT[d][h] = 2 * (1/Z) * v[h][d]; pair splits h range (float4 each)
        float inv2 = 2.f / Z;
        const int h0 = eh * 4;
        float4 w;
        w.x = sv[h0 + 0][d] * inv2;
        w.y = sv[h0 + 1][d] * inv2;
        w.z = sv[h0 + 2][d] * inv2;
        w.w = sv[h0 + 3][d] * inv2;
        *(float4*)&svT[d][h0] = w;
    }
    __syncthreads();

    // output: thread (e = t>>1, dh = t&1) accumulates 32 d's; pair combined
    // via shfl; dh==0 lane writes one 16B fp16 store in scramble layout.
    {
        const int e = t >> 1, dh = t & 1, d0 = dh << 5;
        float o[8] = {0, 0, 0, 0, 0, 0, 0, 0};
#pragma unroll
        for (int db = 0; db < 4; db++) {
            uint4 aw = *(const uint4*)&sT[e][d0 + db * 8];
            const __half* ah = (const __half*)&aw;
#pragma unroll
            for (int j = 0; j < 8; j++) {
                float a = __half2float(ah[j]);
                const int d = d0 + db * 8 + j;
                float4 va = *(const float4*)&svT[d][0];
                float4 vb = *(const float4*)&svT[d][4];
                o[0] = fmaf(a, va.x, o[0]);
                o[1] = fmaf(a, va.y, o[1]);
                o[2] = fmaf(a, va.z, o[2]);
                o[3] = fmaf(a, va.w, o[3]);
                o[4] = fmaf(a, vb.x, o[4]);
                o[5] = fmaf(a, vb.y, o[5]);
                o[6] = fmaf(a, vb.z, o[6]);
                o[7] = fmaf(a, vb.w, o[7]);
            }
        }
#pragma unroll
        for (int h = 0; h < 8; h++) o[h] += __shfl_xor_sync(0xffffffffu, o[h], 1);
        if (dh == 0) {
            const int b = pix >> 12;
            const int n = pix & 4095;
            const size_t off =
                ((size_t)(b * 4096 + e * 64 + (n >> 6))) * CDIM + (n & 63) * 8;
            union { uint4 u; __half hh[8]; } U;
#pragma unroll
            for (int h = 0; h < 8; h++) U.hh[h] = __float2half(o[h]);
            *(uint4*)(scr + off) = U.u;
        }
    }
}

// ---------------------------------------------------------------------------
extern "C" void kernel_launch(void* const* d_in, const int* in_sizes, int n_in,
                              void* d_out, int out_size)
{
    const float* x     = (const float*)d_in[0];
    const float* Wq    = (const float*)d_in[1];
    const float* Wk    = (const float*)d_in[2];
    const float* Wv    = (const float*)d_in[3];
    // d_in[4] = conv_w: dead in the reference
    const float* projw = (const float*)d_in[5];
    const float* projb = (const float*)d_in[6];
    float* out = (float*)d_out;

    cudaFuncSetAttribute(gemm_f16, cudaFuncAttributeMaxDynamicSharedMemorySize, GSMEM);

    __half *x16, *s16, *w16;
    float* qkv;
    cudaGetSymbolAddress((void**)&x16, g_x16);
    cudaGetSymbolAddress((void**)&s16, g_s16);
    cudaGetSymbolAddress((void**)&w16, g_w16);
    cudaGetSymbolAddress((void**)&qkv, g_qkv);

    cvt_x<<<MTOT * CDIM / 4 / 256, 256>>>((const float4*)x, (uint2*)x16, MTOT * CDIM / 4);
    cvt_w<<<dim3(256, 4), 256>>>(
        (const float4*)Wq, (const float4*)Wk, (const float4*)Wv,
        (const float4*)projw, (uint2*)w16);

    // fused QKV GEMM: [16384,512] x [1536,512]^T -> [16384,1536]
    gemm_f16<<<dim3(NQKV / 128, MTOT / 256), 512, GSMEM>>>(x16, w16, nullptr, qkv, NQKV);

    attn_kernel<<<MTOT, 128>>>(qkv, s16);

    // proj GEMM: [16384,512] x [512,512]^T -> out
    gemm_f16<<<dim3(CDIM / 128, MTOT / 256), 512, GSMEM>>>(
        s16, w16 + 3 * CDIM * CDIM, projb, out, CDIM);
}

// round 6
// speedup vs baseline: 3.8969x; 1.4790x over previous
#include <cuda_runtime.h>
#include <cuda_fp16.h>
#include <stdint.h>
#include <math.h>

#define MTOT 16384
#define CDIM 512
#define NQKV 1536

// ---------------------------------------------------------------------------
// Scratch (static __device__: no allocations allowed)
// ---------------------------------------------------------------------------
__device__ __half g_x16[MTOT * CDIM];
__device__ __half g_qkv16[(size_t)MTOT * NQKV];
__device__ __half g_s16[MTOT * CDIM];
__device__ __half g_w16[4 * CDIM * CDIM];   // Wq, Wk, Wv, proj

// ---------------------------------------------------------------------------
// PTX helpers (arch-portable)
// ---------------------------------------------------------------------------
__device__ __forceinline__ uint32_t smem_u32(const void* p) {
    uint32_t a;
    asm("{ .reg .u64 t; cvta.to.shared.u64 t, %1; cvt.u32.u64 %0, t; }"
        : "=r"(a) : "l"(p));
    return a;
}
__device__ __forceinline__ void ldm_x4(uint32_t* r, uint32_t addr) {
    asm volatile("ldmatrix.sync.aligned.m8n8.x4.shared.b16 {%0,%1,%2,%3}, [%4];"
                 : "=r"(r[0]), "=r"(r[1]), "=r"(r[2]), "=r"(r[3]) : "r"(addr));
}
__device__ __forceinline__ void mma_f16(float* d, const uint32_t* a, const uint32_t* b) {
    asm volatile(
        "mma.sync.aligned.m16n8k16.row.col.f32.f16.f16.f32 "
        "{%0,%1,%2,%3}, {%4,%5,%6,%7}, {%8,%9}, {%0,%1,%2,%3};"
        : "+f"(d[0]), "+f"(d[1]), "+f"(d[2]), "+f"(d[3])
        : "r"(a[0]), "r"(a[1]), "r"(a[2]), "r"(a[3]), "r"(b[0]), "r"(b[1]));
}
__device__ __forceinline__ void cp_async16(uint32_t dst, const void* src) {
    asm volatile("cp.async.cg.shared.global [%0], [%1], 16;" :: "r"(dst), "l"(src));
}
#define CP_COMMIT() asm volatile("cp.async.commit_group;" ::: "memory")
#define CP_WAIT(N)  asm volatile("cp.async.wait_group %0;" :: "n"(N) : "memory")

// ---------------------------------------------------------------------------
// fp16 GEMM: C[m,n] = sum_k A[m,k] * B[n,k] (+bias)
// BM=256, BN=128, BK=32, 512 threads, 4-stage cp.async. HOUT: fp16 output.
// ---------------------------------------------------------------------------
#define PITCH 40
#define SH ((256 + 128) * PITCH)
#define OFF_B (256 * PITCH)
#define GSMEM (4 * SH * 2)                  // 122880 B

template <bool HOUT>
__global__ __launch_bounds__(512, 1)
void gemm_f16(const __half* __restrict__ A, const __half* __restrict__ B,
              const float* __restrict__ bias, void* __restrict__ Cv, int ldc)
{
    extern __shared__ __align__(16) __half sm[];
    const int tid = threadIdx.x;
    const int wid = tid >> 5, L = tid & 31;
    const int m0 = blockIdx.y * 256;
    const int n0 = blockIdx.x * 128;
    const int wm = (wid >> 2) * 64;
    const int wn = (wid & 3) * 32;
    const uint32_t sb = smem_u32(sm);

    const __half* Ab = A + (size_t)m0 * CDIM;
    const __half* Bb = B + (size_t)n0 * CDIM;

    float acc[4][4][4];
#pragma unroll
    for (int i = 0; i < 4; i++)
#pragma unroll
        for (int j = 0; j < 4; j++)
#pragma unroll
            for (int q = 0; q < 4; q++) acc[i][j][q] = 0.f;

    const int aRow = L & 15, aK = (L >> 4) * 8;
    const int bRowL = (L & 7) + ((L & 16) ? 8 : 0);
    const int bK = ((L >> 3) & 1) * 8;
    const int lr = tid >> 2, lc = tid & 3;

    auto load_stage = [&](int stage, int k0) {
        const uint32_t s0 = sb + (uint32_t)stage * SH * 2;
        uint32_t doff  = (uint32_t)(lr * PITCH + lc * 8) * 2;
        uint32_t doff2 = (uint32_t)((lr + 128) * PITCH + lc * 8) * 2;
        size_t goff  = (size_t)lr * CDIM + k0 + lc * 8;
        cp_async16(s0 + doff,              Ab + goff);
        cp_async16(s0 + doff2,             Ab + goff + (size_t)128 * CDIM);
        cp_async16(s0 + OFF_B * 2 + doff,  Bb + goff);
    };

    load_stage(0, 0);  CP_COMMIT();
    load_stage(1, 32); CP_COMMIT();
    load_stage(2, 64); CP_COMMIT();

    const int NIT = CDIM / 32;
    for (int s = 0; s < NIT; s++) {
        CP_WAIT(2);
        __syncthreads();
        if (s + 3 < NIT) load_stage((s + 3) & 3, (s + 3) * 32);
        CP_COMMIT();

        const uint32_t pA = sb + (uint32_t)(s & 3) * SH * 2;
        const uint32_t pB = pA + OFF_B * 2;

#pragma unroll
        for (int kk = 0; kk < 32; kk += 16) {
            uint32_t ah[4][4], bh[4][2];
#pragma unroll
            for (int mi = 0; mi < 4; mi++) {
                uint32_t ro = (uint32_t)((wm + mi * 16 + aRow) * PITCH + kk + aK) * 2;
                ldm_x4(ah[mi], pA + ro);
            }
#pragma unroll
            for (int nb = 0; nb < 2; nb++) {
                uint32_t ro = (uint32_t)((wn + nb * 16 + bRowL) * PITCH + kk + bK) * 2;
                uint32_t th[4];
                ldm_x4(th, pB + ro);
                bh[nb * 2][0] = th[0];     bh[nb * 2][1] = th[1];
                bh[nb * 2 + 1][0] = th[2]; bh[nb * 2 + 1][1] = th[3];
            }
#pragma unroll
            for (int mi = 0; mi < 4; mi++)
#pragma unroll
                for (int ni = 0; ni < 4; ni++)
                    mma_f16(acc[mi][ni], ah[mi], bh[ni]);
        }
        __syncthreads();
    }

    const int cr = L >> 2, cc = (L & 3) * 2;
#pragma unroll
    for (int mi = 0; mi < 4; mi++) {
#pragma unroll
        for (int ni = 0; ni < 4; ni++) {
            int row = m0 + wm + mi * 16 + cr;
            int col = n0 + wn + ni * 8 + cc;
            float b0 = 0.f, b1 = 0.f;
            if (bias) { b0 = bias[col]; b1 = bias[col + 1]; }
            if (HOUT) {
                __half* C = (__half*)Cv;
                *(__half2*)&C[(size_t)row * ldc + col] =
                    __floats2half2_rn(acc[mi][ni][0] + b0, acc[mi][ni][1] + b1);
                *(__half2*)&C[(size_t)(row + 8) * ldc + col] =
                    __floats2half2_rn(acc[mi][ni][2] + b0, acc[mi][ni][3] + b1);
            } else {
                float* C = (float*)Cv;
                *(float2*)&C[(size_t)row * ldc + col] =
                    make_float2(acc[mi][ni][0] + b0, acc[mi][ni][1] + b1);
                *(float2*)&C[(size_t)(row + 8) * ldc + col] =
                    make_float2(acc[mi][ni][2] + b0, acc[mi][ni][3] + b1);
            }
        }
    }
}

// ---------------------------------------------------------------------------
// fp32 -> fp16 converts
// ---------------------------------------------------------------------------
__global__ void cvt_x(const float4* __restrict__ src, uint2* __restrict__ dst, int n4)
{
    int i = blockIdx.x * blockDim.x + threadIdx.x;
    if (i >= n4) return;
    float4 v = src[i];
    union { uint2 u; __half b[4]; } H;
    H.b[0] = __float2half(v.x); H.b[1] = __float2half(v.y);
    H.b[2] = __float2half(v.z); H.b[3] = __float2half(v.w);
    dst[i] = H.u;
}

__global__ void cvt_w(const float4* __restrict__ w0, const float4* __restrict__ w1,
                      const float4* __restrict__ w2, const float4* __restrict__ w3,
                      uint2* __restrict__ dst)
{
    int wsel = blockIdx.y;
    const float4* src = (wsel == 0) ? w0 : (wsel == 1) ? w1 : (wsel == 2) ? w2 : w3;
    int i = blockIdx.x * blockDim.x + threadIdx.x;
    float4 v = src[i];
    union { uint2 u; __half b[4]; } H;
    H.b[0] = __float2half(v.x); H.b[1] = __float2half(v.y);
    H.b[2] = __float2half(v.z); H.b[3] = __float2half(v.w);
    dst[(size_t)wsel * 65536 + i] = H.u;
}

// ---------------------------------------------------------------------------
// Per-pixel attention: 64 threads per pixel, 2 pixels per 128-thread block.
// - pitch-68 q/k/v rows: conflict-free gram + column reads
// - q' stored fp16 (one broadcast LDS.128 per e in stage 2)
// - NO MUFU: exp via degree-9 Taylor on the FMA pipe (|S| small; softmax is
//   shift-invariant and scores are bounded, so no max subtraction needed)
// - sT pitch 66 halfs: conflict-free LDS.32 in the output loop
// - 1/Z and the v+v doubling folded into svT
// scr[b, e*64 + n/64, (n%64)*8 + h] = 2*out[b,n,h,e], fp16.
// ---------------------------------------------------------------------------
#define PQ 68

struct __align__(16) PixS {
    float q[8 * PQ];
    float k[8 * PQ];
    float v[8 * PQ];
    float rn[24];
    float sA[64];
    __half qT[64 * 8];     // q'[e][h], 16B rows
    float svT[64 * 8];     // 2/Z_d * v[h][d] at svT[d*8+h]
    __half sT[64 * 66];    // exp(S)[e*66 + d]
};

__global__ __launch_bounds__(128) void attn_kernel(
    const __half* __restrict__ QKV, __half* __restrict__ scr)
{
    __shared__ PixS ps[2];
    const int t = threadIdx.x;
    const int gsel = t >> 6, t6 = t & 63;
    PixS& S = ps[gsel];
    const int pix = blockIdx.x * 2 + gsel;

    // load fp16 qkv -> fp32 padded smem
    {
        const uint4* src = (const uint4*)(QKV + (size_t)pix * NQKV);
#pragma unroll
        for (int j = 0; j < 3; j++) {
            int i = j * 64 + t6;
            union { uint4 u; __half h[8]; } U;
            U.u = src[i];
            float* rowp = (j == 0 ? S.q : j == 1 ? S.k : S.v)
                        + (t6 >> 3) * PQ + (t6 & 7) * 8;
            float4 f0 = make_float4(__half2float(U.h[0]), __half2float(U.h[1]),
                                    __half2float(U.h[2]), __half2float(U.h[3]));
            float4 f1 = make_float4(__half2float(U.h[4]), __half2float(U.h[5]),
                                    __half2float(U.h[6]), __half2float(U.h[7]));
            ((float4*)rowp)[0] = f0;
            ((float4*)rowp)[1] = f1;
        }
    }
    __syncthreads();

    // inverse norms: rn[which*8+h]
    if (t6 < 24) {
        int which = t6 >> 3, h = t6 & 7;
        const float* p = (which == 0 ? S.q : which == 1 ? S.k : S.v) + h * PQ;
        float s = 0.f;
#pragma unroll
        for (int i = 0; i < 16; i++) {
            float4 x = ((const float4*)p)[i];
            s = fmaf(x.x, x.x, fmaf(x.y, x.y, fmaf(x.z, x.z, fmaf(x.w, x.w, s))));
        }
        S.rn[t6] = 1.f / fmaxf(sqrtf(s), 1e-12f);
    }
    __syncthreads();

    // gram of normalized v (all 64 threads; conflict-free float4 broadcasts)
    {
        int h = t6 >> 3, g = t6 & 7;
        const float4* ph = (const float4*)(S.v + h * PQ);
        const float4* pg = (const float4*)(S.v + g * PQ);
        float s = 0.f;
#pragma unroll
        for (int i = 0; i < 16; i++) {
            float4 a = ph[i], b = pg[i];
            s = fmaf(a.x, b.x, fmaf(a.y, b.y, fmaf(a.z, b.z, fmaf(a.w, b.w, s))));
        }
        S.sA[t6] = s * S.rn[16 + h] * S.rn[16 + g];
    }
    __syncthreads();

    // head-mix softmax rows (cosine sims in [-1,1]: no max needed)
    if (t6 < 8) {
        float e[8], sum = 0.f;
#pragma unroll
        for (int g = 0; g < 8; g++) { e[g] = __expf(S.sA[t6 * 8 + g]); sum += e[g]; }
        float inv = 1.f / sum;
#pragma unroll
        for (int g = 0; g < 8; g++) S.sA[t6 * 8 + g] = e[g] * inv;
    }
    __syncthreads();

    // head mix at column d = t6: q' -> fp16 qT (coalesced STS.128), k' -> regs
    float k2[8];
    {
        const int d = t6;
        float qc[8], kc[8];
#pragma unroll
        for (int g = 0; g < 8; g++) {
            qc[g] = S.q[g * PQ + d] * S.rn[g];
            kc[g] = S.k[g * PQ + d] * S.rn[8 + g];
        }
        union { uint4 u; __half hh[8]; } QP;
#pragma unroll
        for (int h = 0; h < 8; h++) {
            float s1 = 0.f, s2 = 0.f;
#pragma unroll
            for (int g = 0; g < 8; g++) {
                s1 = fmaf(S.sA[h * 8 + g], qc[g], s1);
                s2 = fmaf(S.sA[h * 8 + g], kc[g], s2);
            }
            QP.hh[h] = __float2half(s1);
            k2[h] = s2;
        }
        *(uint4*)(S.qT + d * 8) = QP.u;
    }
    __syncthreads();

    // stage 2, thread d: polynomial exp, single pass, Z local
    {
        const int d = t6;
        float Z = 0.f;
#pragma unroll 8
        for (int e = 0; e < 64; e++) {
            union { uint4 u; __half2 h2[4]; } U;
            U.u = *(const uint4*)(S.qT + e * 8);      // broadcast
            float2 f0 = __half22float2(U.h2[0]);
            float2 f1 = __half22float2(U.h2[1]);
            float2 f2 = __half22float2(U.h2[2]);
            float2 f3 = __half22float2(U.h2[3]);
            float s = k2[0] * f0.x;
            s = fmaf(k2[1], f0.y, s);
            s = fmaf(k2[2], f1.x, s);
            s = fmaf(k2[3], f1.y, s);
            s = fmaf(k2[4], f2.x, s);
            s = fmaf(k2[5], f2.y, s);
            s = fmaf(k2[6], f3.x, s);
            s = fmaf(k2[7], f3.y, s);
            // exp(s), |s| small: degree-9 Taylor (Horner)
            float p = fmaf(2.7557319e-6f, s, 2.4801587e-5f);
            p = fmaf(p, s, 1.9841270e-4f);
            p = fmaf(p, s, 1.3888889e-3f);
            p = fmaf(p, s, 8.3333333e-3f);
            p = fmaf(p, s, 4.1666667e-2f);
            p = fmaf(p, s, 1.6666667e-1f);
            p = fmaf(p, s, 0.5f);
            p = fmaf(p, s, 1.0f);
            p = fmaf(p, s, 1.0f);
            Z += p;
            S.sT[e * 66 + d] = __float2half(p);
        }
        float inv2 = 2.f / Z;
        float4 a, b;
        a.x = S.v[0 * PQ + d] * inv2;
        a.y = S.v[1 * PQ + d] * inv2;
        a.z = S.v[2 * PQ + d] * inv2;
        a.w = S.v[3 * PQ + d] * inv2;
        b.x = S.v[4 * PQ + d] * inv2;
        b.y = S.v[5 * PQ + d] * inv2;
        b.z = S.v[6 * PQ + d] * inv2;
        b.w = S.v[7 * PQ + d] * inv2;
        *(float4*)(S.svT + d * 8) = a;
        *(float4*)(S.svT + d * 8 + 4) = b;
    }
    __syncthreads();

    // output, thread e: conflict-free LDS.32 sT row + broadcast svT
    {
        const int e = t6;
        float o[8] = {0, 0, 0, 0, 0, 0, 0, 0};
        const __half2* prow = (const __half2*)(S.sT + e * 66);
#pragma unroll 8
        for (int dd = 0; dd < 32; dd++) {
            float2 a = __half22float2(prow[dd]);
            const float4* v0 = (const float4*)(S.svT + (2 * dd) * 8);
            float4 va = v0[0], vb = v0[1];
            o[0] = fmaf(a.x, va.x, o[0]);
            o[1] = fmaf(a.x, va.y, o[1]);
            o[2] = fmaf(a.x, va.z, o[2]);
            o[3] = fmaf(a.x, va.w, o[3]);
            o[4] = fmaf(a.x, vb.x, o[4]);
            o[5] = fmaf(a.x, vb.y, o[5]);
            o[6] = fmaf(a.x, vb.z, o[6]);
            o[7] = fmaf(a.x, vb.w, o[7]);
            const float4* v1 = (const float4*)(S.svT + (2 * dd + 1) * 8);
            va = v1[0]; vb = v1[1];
            o[0] = fmaf(a.y, va.x, o[0]);
            o[1] = fmaf(a.y, va.y, o[1]);
            o[2] = fmaf(a.y, va.z, o[2]);
            o[3] = fmaf(a.y, va.w, o[3]);
            o[4] = fmaf(a.y, vb.x, o[4]);
            o[5] = fmaf(a.y, vb.y, o[5]);
            o[6] = fmaf(a.y, vb.z, o[6]);
            o[7] = fmaf(a.y, vb.w, o[7]);
        }
        const int b = pix >> 12;
        const int n = pix & 4095;
        const size_t off =
            ((size_t)(b * 4096 + e * 64 + (n >> 6))) * CDIM + (n & 63) * 8;
        union { uint4 u; __half hh[8]; } O;
#pragma unroll
        for (int h = 0; h < 8; h++) O.hh[h] = __float2half(o[h]);
        *(uint4*)(scr + off) = O.u;
    }
}

// ---------------------------------------------------------------------------
extern "C" void kernel_launch(void* const* d_in, const int* in_sizes, int n_in,
                              void* d_out, int out_size)
{
    const float* x     = (const float*)d_in[0];
    const float* Wq    = (const float*)d_in[1];
    const float* Wk    = (const float*)d_in[2];
    const float* Wv    = (const float*)d_in[3];
    // d_in[4] = conv_w: dead in the reference
    const float* projw = (const float*)d_in[5];
    const float* projb = (const float*)d_in[6];
    float* out = (float*)d_out;

    cudaFuncSetAttribute(gemm_f16<true>, cudaFuncAttributeMaxDynamicSharedMemorySize, GSMEM);
    cudaFuncSetAttribute(gemm_f16<false>, cudaFuncAttributeMaxDynamicSharedMemorySize, GSMEM);

    __half *x16, *s16, *w16, *qkv16;
    cudaGetSymbolAddress((void**)&x16, g_x16);
    cudaGetSymbolAddress((void**)&s16, g_s16);
    cudaGetSymbolAddress((void**)&w16, g_w16);
    cudaGetSymbolAddress((void**)&qkv16, g_qkv16);

    cvt_x<<<MTOT * CDIM / 4 / 256, 256>>>((const float4*)x, (uint2*)x16, MTOT * CDIM / 4);
    cvt_w<<<dim3(256, 4), 256>>>(
        (const float4*)Wq, (const float4*)Wk, (const float4*)Wv,
        (const float4*)projw, (uint2*)w16);

    // fused QKV GEMM: [16384,512] x [1536,512]^T -> fp16 [16384,1536]
    gemm_f16<true><<<dim3(NQKV / 128, MTOT / 256), 512, GSMEM>>>(
        x16, w16, nullptr, qkv16, NQKV);

    attn_kernel<<<MTOT / 2, 128>>>(qkv16, s16);

    // proj GEMM: [16384,512] x [512,512]^T -> fp32 out
    gemm_f16<false><<<dim3(CDIM / 128, MTOT / 256), 512, GSMEM>>>(
        s16, w16 + 3 * CDIM * CDIM, projb, out, CDIM);
}